// round 14
// baseline (speedup 1.0000x reference)
#include <cuda_runtime.h>
#include <cuda_fp16.h>
#include <cstdint>

#define NB    2
#define SEQ   4096
#define HID   512
#define NHEAD 8
#define HDIM  64
#define BM    256
#define BN    64
#define NITER (SEQ / BN)
#define L2E   1.44269504088896340736f

typedef unsigned int u32;

// word permutation inside an 8-word (16-half) chunk: logical word w ->
// slot (w&3)*2 | (w>>2). Fragment word pairs (w, w+4) become adjacent
// -> one LDS.64 per B-fragment.
#define PW(w) ((((w) & 3) << 1) | ((w) >> 2))
#define RSTR 40   // u32 words per row: 64-bit phases conflict-free

__device__ __forceinline__ u32 pack2h(float a, float b) {
    __half2 h = __floats2half2_rn(a, b);
    return *(u32*)&h;
}
__device__ __forceinline__ float ex2f(float x) {
    float y; asm("ex2.approx.ftz.f32 %0, %1;" : "=f"(y) : "f"(x)); return y;
}
// D += A @ B  (m16n8k16, fp16 in, fp32 acc)
__device__ __forceinline__ void mma16816(float* c, const u32* a, u32 b0, u32 b1) {
    asm volatile(
        "mma.sync.aligned.m16n8k16.row.col.f32.f16.f16.f32 "
        "{%0,%1,%2,%3}, {%4,%5,%6,%7}, {%8,%9}, {%0,%1,%2,%3};"
        : "+f"(c[0]), "+f"(c[1]), "+f"(c[2]), "+f"(c[3])
        : "r"(a[0]), "r"(a[1]), "r"(a[2]), "r"(a[3]), "r"(b0), "r"(b1));
}

__device__ float g_ctx[NB * SEQ * HID];

// ---------------------------------------------------------------------------
// Flash attention, BM=256, 512 threads (16 warps x 16 q-rows). 4 warps per
// SMSP so HMMA / LDS / MUFU / staging of different warps overlap — the occ2
// effect without the register wall (~95 regs/thread, no spills).
// Double-buffered K/V, LDG prefetch regs, interleaved STS, 1 sync/tile,
// kcp blocks, LDS.64 paired B-fragments. Single-pass fp16 QK/PV, fp32 acc,
// no-max softmax.
// ---------------------------------------------------------------------------
__global__ void __launch_bounds__(512, 1)
attn_kernel(const float* __restrict__ Q, const float* __restrict__ K,
            const float* __restrict__ V, const float* __restrict__ sigma,
            const float* __restrict__ lam_p)
{
    __shared__ __align__(16) u32 sK[2][BN][RSTR];     // [stage][token][chunked d]
    __shared__ __align__(16) u32 sV[2][HDIM][RSTR];   // [stage][d][chunked token]

    const int tid  = threadIdx.x;
    const int warp = tid >> 5;        // 0..15
    const int lane = tid & 31;
    const int r    = lane >> 2;
    const int c    = lane & 3;

    const int bb = blockIdx.y >> 3;
    const int hh = blockIdx.y & 7;
    const int qbase = blockIdx.x * BM;

    float sc = fminf(fmaxf(sigma[bb], 0.001f), 0.2f);
    float sn = (sc - 0.001f) * (1.0f / 0.199f);
    const float rC = lam_p[0] * 0.1f * sn * (1.0f / ((float)SEQ * (float)SEQ)) * L2E;

    const float* Kb = K + (size_t)bb * SEQ * HID + hh * HDIM;
    const float* Vb = V + (size_t)bb * SEQ * HID + hh * HDIM;

    // staging geometry (512 threads)
    const int k_tok  = tid >> 3;              // K: token row (0..63)
    const int k_half = tid & 7;               // K: 8-half slice
    const int k_ch   = k_half >> 1;           // chunk 0..3
    const int k_lwb  = (k_half & 1) * 4;      // logical word base 0 or 4
    const int v_p    = tid & 31;              // V: token pair (0..31)
    const int v_d0   = (tid >> 5) * 4;        // V: 4 d's (0..60)
    const int v_w    = (v_p >> 3) * 8 + PW(v_p & 7);

    float4 kreg[2], vreg[2];

#define LOAD_K(nb) do { \
    const float* _kr = Kb + (size_t)((nb) + k_tok) * HID + k_half * 8; \
    kreg[0] = ((const float4*)_kr)[0]; kreg[1] = ((const float4*)_kr)[1]; \
} while (0)
#define LOAD_V(nb) do { \
    const float* _v0 = Vb + (size_t)((nb) + 2 * v_p) * HID + v_d0; \
    vreg[0] = *(const float4*)_v0; \
    vreg[1] = *(const float4*)(_v0 + HID); \
} while (0)
#define STAGE_K(buf) do { \
    u32* _row = &sK[buf][k_tok][k_ch * 8]; \
    float _f[8] = {kreg[0].x, kreg[0].y, kreg[0].z, kreg[0].w, \
                   kreg[1].x, kreg[1].y, kreg[1].z, kreg[1].w}; \
    _Pragma("unroll") \
    for (int _j = 0; _j < 4; _j++) \
        _row[PW(k_lwb + _j)] = pack2h(_f[2 * _j], _f[2 * _j + 1]); \
} while (0)
#define STAGE_V(buf) do { \
    float _a[4] = {vreg[0].x, vreg[0].y, vreg[0].z, vreg[0].w}; \
    float _b[4] = {vreg[1].x, vreg[1].y, vreg[1].z, vreg[1].w}; \
    _Pragma("unroll") \
    for (int _k = 0; _k < 4; _k++) \
        sV[buf][v_d0 + _k][v_w] = pack2h(_a[_k], _b[_k]); \
} while (0)

    // ---- Q fragments (persistent): 1 m-frag (16 rows) x 16 words, scaled
    u32 qf[16];
    {
        const float* Qb = Q + (size_t)bb * SEQ * HID + hh * HDIM;
        const float s = 0.125f * L2E;
        const int row0 = qbase + warp * 16 + r;
        const float* q0 = Qb + (size_t)row0 * HID;
        const float* q1 = q0 + 8 * HID;
        #pragma unroll
        for (int kc = 0; kc < 4; kc++) {
            int d = kc * 16 + 2 * c;
            qf[kc * 4 + 0] = pack2h(q0[d] * s,     q0[d + 1] * s);
            qf[kc * 4 + 1] = pack2h(q1[d] * s,     q1[d + 1] * s);
            qf[kc * 4 + 2] = pack2h(q0[d + 8] * s, q0[d + 9] * s);
            qf[kc * 4 + 3] = pack2h(q1[d + 8] * s, q1[d + 9] * s);
        }
    }

    float oacc[8][4];
    #pragma unroll
    for (int i = 0; i < 8; i++)
        #pragma unroll
        for (int j = 0; j < 4; j++) oacc[i][j] = 0.0f;
    float l0 = 0.0f, l1 = 0.0f;

    const float fi0 = (float)(qbase + warp * 16 + r);
    const float fi1 = fi0 + 8.0f;

    // ---- prologue: stage tile 0 into buffer 0
    LOAD_K(0);
    LOAD_V(0);
    STAGE_K(0);
    STAGE_V(0);
    __syncthreads();

    for (int kt = 0; kt < NITER; kt++) {
        const int kbase = kt * BN;
        const int cur = kt & 1;
        const int nxt = cur ^ 1;
        const bool has_next = (kt + 1 < NITER);

        if (has_next) { LOAD_K(kbase + BN); LOAD_V(kbase + BN); }

        // ---- 4 blocks: QK(2 n-frags) -> softmax -> PV chunk
        #pragma unroll
        for (int kcp = 0; kcp < 4; kcp++) {
            float sacc[2][4];
            #pragma unroll
            for (int h = 0; h < 2; h++)
                #pragma unroll
                for (int j = 0; j < 4; j++) sacc[h][j] = 0.0f;

            #pragma unroll
            for (int kc = 0; kc < 4; kc++) {
                const int kw = kc * 8 + 2 * c;
                #pragma unroll
                for (int h = 0; h < 2; h++) {
                    const int nt = kcp * 2 + h;
                    uint2 bbv = *(const uint2*)&sK[cur][nt * 8 + r][kw];
                    mma16816(sacc[h], &qf[kc * 4], bbv.x, bbv.y);
                }
            }

            // softmax for these 16 token columns
            u32 pah[4];
            #pragma unroll
            for (int h = 0; h < 2; h++) {
                const float jb = (float)(kbase + (kcp * 2 + h) * 8 + 2 * c);
                float d00 = fi0 - jb, d01 = d00 - 1.0f;
                float d10 = fi1 - jb, d11 = d10 - 1.0f;
                float p00 = ex2f(fmaf(-rC * d00, d00, sacc[h][0]));
                float p01 = ex2f(fmaf(-rC * d01, d01, sacc[h][1]));
                float p10 = ex2f(fmaf(-rC * d10, d10, sacc[h][2]));
                float p11 = ex2f(fmaf(-rC * d11, d11, sacc[h][3]));
                l0 += p00 + p01;
                l1 += p10 + p11;
                pah[h * 2 + 0] = pack2h(p00, p01);
                pah[h * 2 + 1] = pack2h(p10, p11);
            }

            // PV for this 16-token chunk
            const int kw = kcp * 8 + 2 * c;
            #pragma unroll
            for (int ntv = 0; ntv < 8; ntv++) {
                uint2 bbv = *(const uint2*)&sV[cur][ntv * 8 + r][kw];
                mma16816(oacc[ntv], pah, bbv.x, bbv.y);
            }

            if (kcp == 1 && has_next) STAGE_K(nxt);
            if (kcp == 3 && has_next) STAGE_V(nxt);
        }

        __syncthreads();   // buf[nxt] staged; buf[cur] reads complete
    }

    // ---- reduce l across the 4 lanes of each row group, normalize, store
    l0 += __shfl_xor_sync(0xffffffffu, l0, 1);
    l0 += __shfl_xor_sync(0xffffffffu, l0, 2);
    l1 += __shfl_xor_sync(0xffffffffu, l1, 1);
    l1 += __shfl_xor_sync(0xffffffffu, l1, 2);
    const float inv0 = 1.0f / l0;
    const float inv1 = 1.0f / l1;

    const int row0 = qbase + warp * 16 + r;
    float* g0 = g_ctx + ((size_t)bb * SEQ + row0) * HID + hh * HDIM + 2 * c;
    float* g1 = g0 + 8 * HID;
    #pragma unroll
    for (int ntv = 0; ntv < 8; ntv++) {
        *(float2*)(g0 + ntv * 8) = make_float2(oacc[ntv][0] * inv0, oacc[ntv][1] * inv0);
        *(float2*)(g1 + ntv * 8) = make_float2(oacc[ntv][2] * inv1, oacc[ntv][3] * inv1);
    }
}

// ---------------------------------------------------------------------------
// out = ctx @ W^T + b  (M=8192, N=512, K=512) — single-pass fp16 HMMA.
// Proven round-9 version: 128x128 tile, PCH=32, PSTR=40 halfs.
// ---------------------------------------------------------------------------
#define PCH 32
#define PSTR 40

__global__ void __launch_bounds__(256, 2)
proj_kernel(const float* __restrict__ W, const float* __restrict__ bias,
            float* __restrict__ out)
{
    __shared__ __align__(16) __half sA[128][PSTR];
    __shared__ __align__(16) __half sW[128][PSTR];

    const int tid  = threadIdx.x;
    const int warp = tid >> 5;
    const int lane = tid & 31;
    const int r    = lane >> 2;
    const int c    = lane & 3;
    const int mw   = warp & 3;
    const int nw   = warp >> 2;

    const int mbase = blockIdx.x * 128;
    const int nbase = blockIdx.y * 128;

    const int r2 = tid >> 1;
    const int h2 = (tid & 1) * 16;

    float acc[2][8][4];
    #pragma unroll
    for (int mf = 0; mf < 2; mf++)
        #pragma unroll
        for (int nf = 0; nf < 8; nf++)
            #pragma unroll
            for (int j = 0; j < 4; j++) acc[mf][nf][j] = 0.0f;

    for (int kc = 0; kc < HID / PCH; kc++) {
        const int k0 = kc * PCH;
        __syncthreads();
        {
            const float* ar = g_ctx + (size_t)(mbase + r2) * HID + k0 + h2;
            #pragma unroll
            for (int i = 0; i < 4; i++) {
                float4 v = ((const float4*)ar)[i];
                *(u32*)&sA[r2][h2 + i * 4]     = pack2h(v.x, v.y);
                *(u32*)&sA[r2][h2 + i * 4 + 2] = pack2h(v.z, v.w);
            }
            const float* wr = W + (size_t)(nbase + r2) * HID + k0 + h2;
            #pragma unroll
            for (int i = 0; i < 4; i++) {
                float4 v = ((const float4*)wr)[i];
                *(u32*)&sW[r2][h2 + i * 4]     = pack2h(v.x, v.y);
                *(u32*)&sW[r2][h2 + i * 4 + 2] = pack2h(v.z, v.w);
            }
        }
        __syncthreads();

        #pragma unroll
        for (int kf = 0; kf < 2; kf++) {
            const int kk = kf * 16 + 2 * c;
            u32 ah[2][4];
            #pragma unroll
            for (int mf = 0; mf < 2; mf++) {
                const int m0 = mw * 32 + mf * 16;
                ah[mf][0] = *(const u32*)&sA[m0 + r][kk];
                ah[mf][1] = *(const u32*)&sA[m0 + r + 8][kk];
                ah[mf][2] = *(const u32*)&sA[m0 + r][kk + 8];
                ah[mf][3] = *(const u32*)&sA[m0 + r + 8][kk + 8];
            }
            #pragma unroll
            for (int nf = 0; nf < 8; nf++) {
                const int n0 = nw * 64 + nf * 8 + r;
                u32 b0 = *(const u32*)&sW[n0][kk];
                u32 b1 = *(const u32*)&sW[n0][kk + 8];
                mma16816(acc[0][nf], ah[0], b0, b1);
                mma16816(acc[1][nf], ah[1], b0, b1);
            }
        }
    }

    #pragma unroll
    for (int nf = 0; nf < 8; nf++) {
        const int n = nbase + nw * 64 + nf * 8 + 2 * c;
        const float bv0 = bias[n], bv1 = bias[n + 1];
        #pragma unroll
        for (int mf = 0; mf < 2; mf++) {
            const int m = mbase + mw * 32 + mf * 16 + r;
            *(float2*)&out[(size_t)m * HID + n] =
                make_float2(acc[mf][nf][0] + bv0, acc[mf][nf][1] + bv1);
            *(float2*)&out[(size_t)(m + 8) * HID + n] =
                make_float2(acc[mf][nf][2] + bv0, acc[mf][nf][3] + bv1);
        }
    }
}

extern "C" void kernel_launch(void* const* d_in, const int* in_sizes, int n_in,
                              void* d_out, int out_size)
{
    const float* Q     = (const float*)d_in[0];
    const float* K     = (const float*)d_in[1];
    const float* V     = (const float*)d_in[2];
    const float* sigma = (const float*)d_in[3];
    const float* lam   = (const float*)d_in[4];
    const float* W     = (const float*)d_in[5];
    const float* bias  = (const float*)d_in[6];
    float* out = (float*)d_out;

    dim3 g1(SEQ / BM, NB * NHEAD);
    attn_kernel<<<g1, 512>>>(Q, K, V, sigma, lam);

    dim3 g2(NB * SEQ / 128, HID / 128);
    proj_kernel<<<g2, 256>>>(W, bias, out);
}

// round 15
// speedup vs baseline: 1.1827x; 1.1827x over previous
#include <cuda_runtime.h>
#include <cuda_fp16.h>
#include <cstdint>

#define NB    2
#define SEQ   4096
#define HID   512
#define NHEAD 8
#define HDIM  64
#define BM    256
#define BN    64
#define NITER (SEQ / BN)
#define L2E   1.44269504088896340736f

#define KSTR 72   // halfs per row (144 B): LDSM rows stride 9 granules -> conflict-free

typedef unsigned int u32;

__device__ __forceinline__ u32 pack2h(float a, float b) {
    __half2 h = __floats2half2_rn(a, b);
    return *(u32*)&h;
}
__device__ __forceinline__ float ex2f(float x) {
    float y; asm("ex2.approx.ftz.f32 %0, %1;" : "=f"(y) : "f"(x)); return y;
}
__device__ __forceinline__ u32 cvta_smem(const void* p) {
    return (u32)__cvta_generic_to_shared(p);
}
// D += A @ B  (m16n8k16, fp16 in, fp32 acc)
__device__ __forceinline__ void mma16816(float* c, const u32* a, u32 b0, u32 b1) {
    asm volatile(
        "mma.sync.aligned.m16n8k16.row.col.f32.f16.f16.f32 "
        "{%0,%1,%2,%3}, {%4,%5,%6,%7}, {%8,%9}, {%0,%1,%2,%3};"
        : "+f"(c[0]), "+f"(c[1]), "+f"(c[2]), "+f"(c[3])
        : "r"(a[0]), "r"(a[1]), "r"(a[2]), "r"(a[3]), "r"(b0), "r"(b1));
}
#define LDSM4(r0, r1, r2, r3, addr) \
    asm volatile("ldmatrix.sync.aligned.m8n8.x4.shared.b16 {%0,%1,%2,%3}, [%4];" \
        : "=r"(r0), "=r"(r1), "=r"(r2), "=r"(r3) : "r"(addr))

// ctx scratch in fp16 pairs (proj quantizes to fp16 anyway — identical values)
__device__ u32 g_ctx[NB * SEQ * HID / 2];

// ---------------------------------------------------------------------------
// Flash attention, BM=256, 8 warps, occ1 (r11 structure). B-fragments via
// ldmatrix.x4 (1 op = 4 frags). Natural SMEM layout, STS.128 K staging.
// Double-buffered K/V, LDG prefetch, interleaved STS, 1 sync/tile.
// Single-pass fp16 QK/PV, fp32 acc, no-max softmax.
// ---------------------------------------------------------------------------
__global__ void __launch_bounds__(256, 1)
attn_kernel(const float* __restrict__ Q, const float* __restrict__ K,
            const float* __restrict__ V, const float* __restrict__ sigma,
            const float* __restrict__ lam_p)
{
    __shared__ __align__(16) __half sK[2][BN][KSTR];     // [stage][token][d]
    __shared__ __align__(16) __half sV[2][HDIM][KSTR];   // [stage][d][token]

    const int tid  = threadIdx.x;
    const int warp = tid >> 5;
    const int lane = tid & 31;
    const int r    = lane >> 2;
    const int c    = lane & 3;

    const int bb = blockIdx.y >> 3;
    const int hh = blockIdx.y & 7;
    const int qbase = blockIdx.x * BM;

    float sc = fminf(fmaxf(sigma[bb], 0.001f), 0.2f);
    float sn = (sc - 0.001f) * (1.0f / 0.199f);
    const float rC = lam_p[0] * 0.1f * sn * (1.0f / ((float)SEQ * (float)SEQ)) * L2E;

    const float* Kb = K + (size_t)bb * SEQ * HID + hh * HDIM;
    const float* Vb = V + (size_t)bb * SEQ * HID + hh * HDIM;

    const int k_tok  = tid >> 2;          // K staging: token row
    const int k_part = tid & 3;           // K staging: 16-half slice
    const int v_p    = tid & 31;          // V staging: token pair
    const int v_d0   = (tid >> 5) * 8;    // V staging: 8 d's

    // ldmatrix per-lane address offsets (bytes)
    const u32 kq_off = (u32)(lane & 7) * (KSTR * 2) + (u32)(lane >> 3) * 16;
    const u32 pv_off = ((u32)(lane >> 4) * 8 + (u32)(lane & 7)) * (KSTR * 2)
                     + ((u32)(lane >> 3) & 1) * 16;
    u32 skb[2], svb[2];
    skb[0] = cvta_smem(&sK[0][0][0]); skb[1] = cvta_smem(&sK[1][0][0]);
    svb[0] = cvta_smem(&sV[0][0][0]); svb[1] = cvta_smem(&sV[1][0][0]);

    float4 kreg[4], vreg[4];

#define LOAD_K(nb) do { \
    const float* _kr = Kb + (size_t)((nb) + k_tok) * HID + k_part * 16; \
    kreg[0] = ((const float4*)_kr)[0]; kreg[1] = ((const float4*)_kr)[1]; \
    kreg[2] = ((const float4*)_kr)[2]; kreg[3] = ((const float4*)_kr)[3]; \
} while (0)
#define LOAD_V(nb) do { \
    const float* _v0 = Vb + (size_t)((nb) + 2 * v_p) * HID + v_d0; \
    const float* _v1 = _v0 + HID; \
    vreg[0] = ((const float4*)_v0)[0]; vreg[1] = ((const float4*)_v1)[0]; \
    vreg[2] = ((const float4*)_v0)[1]; vreg[3] = ((const float4*)_v1)[1]; \
} while (0)
#define STAGE_K(buf) do { \
    uint4* _dst = (uint4*)&sK[buf][k_tok][k_part * 16]; \
    _dst[0] = make_uint4(pack2h(kreg[0].x, kreg[0].y), pack2h(kreg[0].z, kreg[0].w), \
                         pack2h(kreg[1].x, kreg[1].y), pack2h(kreg[1].z, kreg[1].w)); \
    _dst[1] = make_uint4(pack2h(kreg[2].x, kreg[2].y), pack2h(kreg[2].z, kreg[2].w), \
                         pack2h(kreg[3].x, kreg[3].y), pack2h(kreg[3].z, kreg[3].w)); \
} while (0)
#define STAGE_V(buf) do { \
    _Pragma("unroll") \
    for (int _i = 0; _i < 2; _i++) { \
        float4 _a = vreg[2 * _i], _b = vreg[2 * _i + 1]; \
        float _av[4] = {_a.x, _a.y, _a.z, _a.w}; \
        float _bv[4] = {_b.x, _b.y, _b.z, _b.w}; \
        _Pragma("unroll") \
        for (int _k = 0; _k < 4; _k++) \
            *(u32*)&sV[buf][v_d0 + _i * 4 + _k][2 * v_p] = pack2h(_av[_k], _bv[_k]); \
    } \
} while (0)

    // ---- Q fragments (persistent): 2 m-frags x 16 words, scaled
    u32 qf[2][16];
    {
        const float* Qb = Q + (size_t)bb * SEQ * HID + hh * HDIM;
        const float s = 0.125f * L2E;
        #pragma unroll
        for (int mf = 0; mf < 2; mf++) {
            const int row0 = qbase + warp * 32 + mf * 16 + r;
            const float* q0 = Qb + (size_t)row0 * HID;
            const float* q1 = q0 + 8 * HID;
            #pragma unroll
            for (int kc = 0; kc < 4; kc++) {
                int d = kc * 16 + 2 * c;
                qf[mf][kc * 4 + 0] = pack2h(q0[d] * s,     q0[d + 1] * s);
                qf[mf][kc * 4 + 1] = pack2h(q1[d] * s,     q1[d + 1] * s);
                qf[mf][kc * 4 + 2] = pack2h(q0[d + 8] * s, q0[d + 9] * s);
                qf[mf][kc * 4 + 3] = pack2h(q1[d + 8] * s, q1[d + 9] * s);
            }
        }
    }

    float oacc[2][8][4];
    #pragma unroll
    for (int mf = 0; mf < 2; mf++)
        #pragma unroll
        for (int i = 0; i < 8; i++)
            #pragma unroll
            for (int j = 0; j < 4; j++) oacc[mf][i][j] = 0.0f;
    float lsum[2][2] = {{0.0f, 0.0f}, {0.0f, 0.0f}};

    const int w32 = warp * 32;

    LOAD_K(0);
    LOAD_V(0);
    STAGE_K(0);
    STAGE_V(0);
    __syncthreads();

    for (int kt = 0; kt < NITER; kt++) {
        const int kbase = kt * BN;
        const int cur = kt & 1;
        const int nxt = cur ^ 1;
        const bool has_next = (kt + 1 < NITER);

        if (has_next) { LOAD_K(kbase + BN); LOAD_V(kbase + BN); }

        // ---- 4 blocks: QK(2 n-frags, LDSM.x4) -> softmax -> PV(LDSM.x4)
        #pragma unroll
        for (int kcp = 0; kcp < 4; kcp++) {
            float sacc[2][2][4];
            #pragma unroll
            for (int mf = 0; mf < 2; mf++)
                #pragma unroll
                for (int h = 0; h < 2; h++)
                    #pragma unroll
                    for (int j = 0; j < 4; j++) sacc[mf][h][j] = 0.0f;

            #pragma unroll
            for (int h = 0; h < 2; h++) {
                const int nt = kcp * 2 + h;
                const u32 base = skb[cur] + (u32)nt * (8 * KSTR * 2) + kq_off;
                u32 b0, b1, b2, b3;
                LDSM4(b0, b1, b2, b3, base);          // kc0, kc1
                mma16816(sacc[0][h], &qf[0][0], b0, b1);
                mma16816(sacc[1][h], &qf[1][0], b0, b1);
                mma16816(sacc[0][h], &qf[0][4], b2, b3);
                mma16816(sacc[1][h], &qf[1][4], b2, b3);
                u32 b4, b5, b6, b7;
                LDSM4(b4, b5, b6, b7, base + 64);     // kc2, kc3
                mma16816(sacc[0][h], &qf[0][8],  b4, b5);
                mma16816(sacc[1][h], &qf[1][8],  b4, b5);
                mma16816(sacc[0][h], &qf[0][12], b6, b7);
                mma16816(sacc[1][h], &qf[1][12], b6, b7);
            }

            // softmax for these 16 token columns
            u32 pah[2][4];
            #pragma unroll
            for (int mf = 0; mf < 2; mf++) {
                const float fi0 = (float)(qbase + w32 + mf * 16 + r);
                const float fi1 = fi0 + 8.0f;
                #pragma unroll
                for (int h = 0; h < 2; h++) {
                    const float jb = (float)(kbase + (kcp * 2 + h) * 8 + 2 * c);
                    float d00 = fi0 - jb, d01 = d00 - 1.0f;
                    float d10 = fi1 - jb, d11 = d10 - 1.0f;
                    float p00 = ex2f(fmaf(-rC * d00, d00, sacc[mf][h][0]));
                    float p01 = ex2f(fmaf(-rC * d01, d01, sacc[mf][h][1]));
                    float p10 = ex2f(fmaf(-rC * d10, d10, sacc[mf][h][2]));
                    float p11 = ex2f(fmaf(-rC * d11, d11, sacc[mf][h][3]));
                    lsum[mf][0] += p00 + p01;
                    lsum[mf][1] += p10 + p11;
                    pah[mf][h * 2 + 0] = pack2h(p00, p01);
                    pah[mf][h * 2 + 1] = pack2h(p10, p11);
                }
            }

            // PV for this 16-token chunk: 4 LDSM.x4 cover all 8 d-octs
            const u32 vbase = svb[cur] + (u32)kcp * 32 + pv_off;
            #pragma unroll
            for (int n2 = 0; n2 < 4; n2++) {
                u32 b0, b1, b2, b3;
                LDSM4(b0, b1, b2, b3, vbase + (u32)n2 * (16 * KSTR * 2));
                mma16816(oacc[0][2 * n2],     pah[0], b0, b1);
                mma16816(oacc[1][2 * n2],     pah[1], b0, b1);
                mma16816(oacc[0][2 * n2 + 1], pah[0], b2, b3);
                mma16816(oacc[1][2 * n2 + 1], pah[1], b2, b3);
            }

            if (kcp == 1 && has_next) STAGE_K(nxt);
            if (kcp == 3 && has_next) STAGE_V(nxt);
        }

        __syncthreads();
    }

    // ---- reduce l, normalize, store ctx as half2 words
    #pragma unroll
    for (int mf = 0; mf < 2; mf++) {
        float l0 = lsum[mf][0], l1 = lsum[mf][1];
        l0 += __shfl_xor_sync(0xffffffffu, l0, 1);
        l0 += __shfl_xor_sync(0xffffffffu, l0, 2);
        l1 += __shfl_xor_sync(0xffffffffu, l1, 1);
        l1 += __shfl_xor_sync(0xffffffffu, l1, 2);
        const float inv0 = 1.0f / l0;
        const float inv1 = 1.0f / l1;

        const int row0 = qbase + w32 + mf * 16 + r;
        u32* g0 = g_ctx + ((size_t)bb * SEQ + row0) * (HID / 2) + hh * (HDIM / 2) + c;
        u32* g1 = g0 + 8 * (HID / 2);
        #pragma unroll
        for (int ntv = 0; ntv < 8; ntv++) {
            g0[ntv * 4] = pack2h(oacc[mf][ntv][0] * inv0, oacc[mf][ntv][1] * inv0);
            g1[ntv * 4] = pack2h(oacc[mf][ntv][2] * inv1, oacc[mf][ntv][3] * inv1);
        }
    }
}

// ---------------------------------------------------------------------------
// out = ctx16 @ W^T + b  (M=8192, N=512, K=512) — fp16 HMMA, ctx already
// fp16 in g_ctx. Double-buffered SMEM + register prefetch: 1 sync/iter.
// ---------------------------------------------------------------------------
#define PCH 32
#define PSTR 40

__global__ void __launch_bounds__(256, 2)
proj_kernel(const float* __restrict__ W, const float* __restrict__ bias,
            float* __restrict__ out)
{
    __shared__ __align__(16) __half sA[2][128][PSTR];
    __shared__ __align__(16) __half sW[2][128][PSTR];

    const int tid  = threadIdx.x;
    const int warp = tid >> 5;
    const int lane = tid & 31;
    const int r    = lane >> 2;
    const int c    = lane & 3;
    const int mw   = warp & 3;
    const int nw   = warp >> 2;

    const int mbase = blockIdx.x * 128;
    const int nbase = blockIdx.y * 128;

    const int r2 = tid >> 1;
    const int h2 = (tid & 1) * 16;   // half offset within 32-half chunk

    uint4 areg[2];
    float4 wreg[4];

#define P_LOAD(k0) do { \
    const uint4* _ar = (const uint4*)(g_ctx + (size_t)(mbase + r2) * (HID / 2) \
                                      + ((k0) + h2) / 2); \
    areg[0] = _ar[0]; areg[1] = _ar[1]; \
    const float* _wr = W + (size_t)(nbase + r2) * HID + (k0) + h2; \
    wreg[0] = ((const float4*)_wr)[0]; wreg[1] = ((const float4*)_wr)[1]; \
    wreg[2] = ((const float4*)_wr)[2]; wreg[3] = ((const float4*)_wr)[3]; \
} while (0)
#define P_STAGE(buf) do { \
    uint4* _da = (uint4*)&sA[buf][r2][h2]; \
    _da[0] = areg[0]; _da[1] = areg[1]; \
    uint4* _dw = (uint4*)&sW[buf][r2][h2]; \
    _dw[0] = make_uint4(pack2h(wreg[0].x, wreg[0].y), pack2h(wreg[0].z, wreg[0].w), \
                        pack2h(wreg[1].x, wreg[1].y), pack2h(wreg[1].z, wreg[1].w)); \
    _dw[1] = make_uint4(pack2h(wreg[2].x, wreg[2].y), pack2h(wreg[2].z, wreg[2].w), \
                        pack2h(wreg[3].x, wreg[3].y), pack2h(wreg[3].z, wreg[3].w)); \
} while (0)

    float acc[2][8][4];
    #pragma unroll
    for (int mf = 0; mf < 2; mf++)
        #pragma unroll
        for (int nf = 0; nf < 8; nf++)
            #pragma unroll
            for (int j = 0; j < 4; j++) acc[mf][nf][j] = 0.0f;

    P_LOAD(0);
    P_STAGE(0);
    __syncthreads();

    for (int kc = 0; kc < HID / PCH; kc++) {
        const int cur = kc & 1;
        const bool has_next = (kc + 1 < HID / PCH);
        if (has_next) P_LOAD((kc + 1) * PCH);

        #pragma unroll
        for (int kf = 0; kf < 2; kf++) {
            const int kk = kf * 16 + 2 * c;
            u32 ah[2][4];
            #pragma unroll
            for (int mf = 0; mf < 2; mf++) {
                const int m0 = mw * 32 + mf * 16;
                ah[mf][0] = *(const u32*)&sA[cur][m0 + r][kk];
                ah[mf][1] = *(const u32*)&sA[cur][m0 + r + 8][kk];
                ah[mf][2] = *(const u32*)&sA[cur][m0 + r][kk + 8];
                ah[mf][3] = *(const u32*)&sA[cur][m0 + r + 8][kk + 8];
            }
            #pragma unroll
            for (int nf = 0; nf < 8; nf++) {
                const int n0 = nw * 64 + nf * 8 + r;
                u32 b0 = *(const u32*)&sW[cur][n0][kk];
                u32 b1 = *(const u32*)&sW[cur][n0][kk + 8];
                mma16816(acc[0][nf], ah[0], b0, b1);
                mma16816(acc[1][nf], ah[1], b0, b1);
            }
        }

        if (has_next) P_STAGE(cur ^ 1);
        __syncthreads();
    }

    #pragma unroll
    for (int nf = 0; nf < 8; nf++) {
        const int n = nbase + nw * 64 + nf * 8 + 2 * c;
        const float bv0 = bias[n], bv1 = bias[n + 1];
        #pragma unroll
        for (int mf = 0; mf < 2; mf++) {
            const int m = mbase + mw * 32 + mf * 16 + r;
            *(float2*)&out[(size_t)m * HID + n] =
                make_float2(acc[mf][nf][0] + bv0, acc[mf][nf][1] + bv1);
            *(float2*)&out[(size_t)(m + 8) * HID + n] =
                make_float2(acc[mf][nf][2] + bv0, acc[mf][nf][3] + bv1);
        }
    }
}

extern "C" void kernel_launch(void* const* d_in, const int* in_sizes, int n_in,
                              void* d_out, int out_size)
{
    const float* Q     = (const float*)d_in[0];
    const float* K     = (const float*)d_in[1];
    const float* V     = (const float*)d_in[2];
    const float* sigma = (const float*)d_in[3];
    const float* lam   = (const float*)d_in[4];
    const float* W     = (const float*)d_in[5];
    const float* bias  = (const float*)d_in[6];
    float* out = (float*)d_out;

    dim3 g1(SEQ / BM, NB * NHEAD);
    attn_kernel<<<g1, 256>>>(Q, K, V, sigma, lam);

    dim3 g2(NB * SEQ / 128, HID / 128);
    proj_kernel<<<g2, 256>>>(W, bias, out);
}